// round 1
// baseline (speedup 1.0000x reference)
#include <cuda_runtime.h>
#include <cuda_bf16.h>
#include <math.h>

// Problem constants
#define NN 100000          // nodes
#define NE 1600000         // edges (without self loops)
#define C  128             // in/hid channels
#define OC 64              // out channels
#define NG 64              // graphs

// ---------------- static device scratch (no cudaMalloc allowed) -------------
__device__ float g_bufA[(size_t)NN * C];   // y  = dinv * (X@W)
__device__ float g_bufB[(size_t)NN * C];   // h  after aggregation+relu
__device__ int   g_src[NE];
__device__ int   g_dst[NE];
__device__ int   g_col[NE];                // CSR column indices (src per dst)
__device__ int   g_cnt[NN];                // in-degree (without self loop)
__device__ int   g_rowptr[NN];             // CSR row start
__device__ int   g_fillptr[NN];            // atomic fill cursor
__device__ float g_dinv[NN];               // deg^-1/2 (deg includes self loop)
__device__ int   g_bsum[128];              // scan block sums
__device__ int   g_batch32[NN];
__device__ int   g_gcnt[NG];
__device__ int   g_goff[NG + 1];
__device__ float g_pool[NG * C];

// ---------------- kernels ---------------------------------------------------

// Detect int32 vs int64 edge_index/batch and repack to int32.
__global__ void k_repack(const void* edge, const void* batch, int E, int N) {
    const int* e32 = (const int*)edge;
    bool is64 = true;
    #pragma unroll
    for (int i = 0; i < 8; i++) if (e32[2 * i + 1] != 0) is64 = false;

    int tid = blockIdx.x * blockDim.x + threadIdx.x;
    int stride = gridDim.x * blockDim.x;
    if (is64) {
        const long long* e64 = (const long long*)edge;
        const long long* b64 = (const long long*)batch;
        for (int i = tid; i < E; i += stride) {
            g_src[i] = (int)e64[i];
            g_dst[i] = (int)e64[(size_t)E + i];
        }
        for (int i = tid; i < N; i += stride) g_batch32[i] = (int)b64[i];
    } else {
        const int* b32 = (const int*)batch;
        for (int i = tid; i < E; i += stride) {
            g_src[i] = e32[i];
            g_dst[i] = e32[E + i];
        }
        for (int i = tid; i < N; i += stride) g_batch32[i] = b32[i];
    }
}

__global__ void k_init(int N) {
    int tid = blockIdx.x * blockDim.x + threadIdx.x;
    int stride = gridDim.x * blockDim.x;
    for (int i = tid; i < N; i += stride) g_cnt[i] = 0;
    if (tid < NG) g_gcnt[tid] = 0;
}

__global__ void k_hist(int E) {
    int tid = blockIdx.x * blockDim.x + threadIdx.x;
    int stride = gridDim.x * blockDim.x;
    for (int e = tid; e < E; e += stride) atomicAdd(&g_cnt[g_dst[e]], 1);
}

__global__ void k_dinv(int N) {
    int i = blockIdx.x * blockDim.x + threadIdx.x;
    if (i < N) g_dinv[i] = rsqrtf((float)(g_cnt[i] + 1));   // +1 self loop
}

// exclusive scan of g_cnt -> g_rowptr, 1024-wide blocks
__global__ void k_scan1(int n) {
    __shared__ int sh[1024];
    int i = blockIdx.x * 1024 + threadIdx.x;
    int v = (i < n) ? g_cnt[i] : 0;
    sh[threadIdx.x] = v;
    __syncthreads();
    for (int off = 1; off < 1024; off <<= 1) {
        int t = (threadIdx.x >= off) ? sh[threadIdx.x - off] : 0;
        __syncthreads();
        sh[threadIdx.x] += t;
        __syncthreads();
    }
    if (i < n) g_rowptr[i] = sh[threadIdx.x] - v;   // exclusive
    if (threadIdx.x == 1023) g_bsum[blockIdx.x] = sh[1023];
}

__global__ void k_scan2(int nb) {
    __shared__ int sh[128];
    int v = (threadIdx.x < nb) ? g_bsum[threadIdx.x] : 0;
    sh[threadIdx.x] = v;
    __syncthreads();
    for (int off = 1; off < 128; off <<= 1) {
        int t = (threadIdx.x >= off) ? sh[threadIdx.x - off] : 0;
        __syncthreads();
        sh[threadIdx.x] += t;
        __syncthreads();
    }
    if (threadIdx.x < nb) g_bsum[threadIdx.x] = sh[threadIdx.x] - v;  // exclusive
}

__global__ void k_scan3(int n) {
    int i = blockIdx.x * blockDim.x + threadIdx.x;
    if (i < n) {
        int r = g_rowptr[i] + g_bsum[i >> 10];
        g_rowptr[i] = r;
        g_fillptr[i] = r;
    }
}

__global__ void k_fill(int E) {
    int tid = blockIdx.x * blockDim.x + threadIdx.x;
    int stride = gridDim.x * blockDim.x;
    for (int e = tid; e < E; e += stride) {
        int d = g_dst[e];
        int p = atomicAdd(&g_fillptr[d], 1);
        g_col[p] = g_src[e];
    }
}

// Y[r, :] = dinv[r] * (X[r, :] @ W)      X: [n,128], W: [128,128]
// Block: 256 threads, tile 64 rows x 128 cols, full W in smem.
__global__ __launch_bounds__(256, 2) void k_gemm(
    const float* __restrict__ X, const float* __restrict__ W,
    float* __restrict__ Y, int n)
{
    __shared__ float Ws[C * C];      // 64 KB
    __shared__ float Xs[64 * C];     // 32 KB
    int tid = threadIdx.x;
    int row0 = blockIdx.x * 64;

    for (int i = tid; i < C * C; i += 256) Ws[i] = W[i];
    for (int i = tid; i < 64 * C; i += 256) {
        int r = row0 + (i >> 7);
        Xs[i] = (r < n) ? X[(size_t)r * C + (i & 127)] : 0.0f;
    }
    __syncthreads();

    int tn = tid & 31;    // column group: cols [tn*4, tn*4+4)
    int tm = tid >> 5;    // row group:    rows [tm*8, tm*8+8) within tile
    float acc[8][4];
    #pragma unroll
    for (int r = 0; r < 8; r++)
        #pragma unroll
        for (int c = 0; c < 4; c++) acc[r][c] = 0.0f;

    #pragma unroll 4
    for (int k = 0; k < C; k++) {
        float4 wv = *(const float4*)&Ws[k * C + tn * 4];
        #pragma unroll
        for (int r = 0; r < 8; r++) {
            float xv = Xs[(tm * 8 + r) * C + k];   // warp-uniform broadcast
            acc[r][0] += xv * wv.x;
            acc[r][1] += xv * wv.y;
            acc[r][2] += xv * wv.z;
            acc[r][3] += xv * wv.w;
        }
    }

    #pragma unroll
    for (int r = 0; r < 8; r++) {
        int row = row0 + tm * 8 + r;
        if (row < n) {
            float s = g_dinv[row];
            float4 o = make_float4(acc[r][0] * s, acc[r][1] * s,
                                   acc[r][2] * s, acc[r][3] * s);
            *(float4*)&Y[(size_t)row * C + tn * 4] = o;
        }
    }
}

// h[i] = relu(dinv[i] * (y[i] + sum_{e in CSR row i} y[col[e]]) + b)
// warp per node, lane handles 4 channels (float4).
__global__ void k_agg(const float* __restrict__ Yin,
                      const float* __restrict__ bias,
                      float* __restrict__ Hout, int n)
{
    int warp = (blockIdx.x * blockDim.x + threadIdx.x) >> 5;
    int lane = threadIdx.x & 31;
    if (warp >= n) return;

    const float4* Y4 = (const float4*)Yin;
    float4 acc = Y4[(size_t)warp * 32 + lane];    // self loop term
    int start = g_rowptr[warp];
    int deg   = g_cnt[warp];
    int e = start, end = start + deg;

    for (; e + 4 <= end; e += 4) {
        int s0 = g_col[e], s1 = g_col[e + 1], s2 = g_col[e + 2], s3 = g_col[e + 3];
        float4 a = Y4[(size_t)s0 * 32 + lane];
        float4 b = Y4[(size_t)s1 * 32 + lane];
        float4 c = Y4[(size_t)s2 * 32 + lane];
        float4 d = Y4[(size_t)s3 * 32 + lane];
        acc.x += a.x + b.x + c.x + d.x;
        acc.y += a.y + b.y + c.y + d.y;
        acc.z += a.z + b.z + c.z + d.z;
        acc.w += a.w + b.w + c.w + d.w;
    }
    for (; e < end; e++) {
        int s = g_col[e];
        float4 a = Y4[(size_t)s * 32 + lane];
        acc.x += a.x; acc.y += a.y; acc.z += a.z; acc.w += a.w;
    }

    float di = g_dinv[warp];
    float4 bv = ((const float4*)bias)[lane];
    float4 o;
    o.x = fmaxf(di * acc.x + bv.x, 0.0f);
    o.y = fmaxf(di * acc.y + bv.y, 0.0f);
    o.z = fmaxf(di * acc.z + bv.z, 0.0f);
    o.w = fmaxf(di * acc.w + bv.w, 0.0f);
    ((float4*)Hout)[(size_t)warp * 32 + lane] = o;
}

__global__ void k_ghist(int N) {
    int tid = blockIdx.x * blockDim.x + threadIdx.x;
    int stride = gridDim.x * blockDim.x;
    for (int i = tid; i < N; i += stride) atomicAdd(&g_gcnt[g_batch32[i]], 1);
}

__global__ void k_goff() {
    if (threadIdx.x == 0 && blockIdx.x == 0) {
        int s = 0;
        for (int g = 0; g < NG; g++) { g_goff[g] = s; s += g_gcnt[g]; }
        g_goff[NG] = s;
    }
}

// one block per graph, one thread per channel
__global__ void k_pool(const float* __restrict__ H) {
    int g = blockIdx.x;
    int c = threadIdx.x;
    int s = g_goff[g], e = g_goff[g + 1];
    float acc = 0.0f;
    int r = s;
    for (; r + 4 <= e; r += 4) {
        acc += H[(size_t)r * C + c] + H[(size_t)(r + 1) * C + c]
             + H[(size_t)(r + 2) * C + c] + H[(size_t)(r + 3) * C + c];
    }
    for (; r < e; r++) acc += H[(size_t)r * C + c];
    float cnt = (float)(e - s);
    g_pool[g * C + c] = acc / fmaxf(cnt, 1.0f);
}

// out[g, o] = g_pool[g, :] @ Wl[:, o] + bl[o]
__global__ void k_head(const float* __restrict__ Wl,
                       const float* __restrict__ bl,
                       float* __restrict__ out)
{
    int g = blockIdx.x;    // 64
    int o = threadIdx.x;   // 64
    float acc = bl[o];
    #pragma unroll 4
    for (int k = 0; k < C; k++) acc += g_pool[g * C + k] * Wl[k * OC + o];
    out[g * OC + o] = acc;
}

// ---------------- launch -----------------------------------------------------
extern "C" void kernel_launch(void* const* d_in, const int* in_sizes, int n_in,
                              void* d_out, int out_size) {
    const float* x   = (const float*)d_in[0];
    const void*  ei  = d_in[1];
    const void*  bat = d_in[2];
    const float* W1  = (const float*)d_in[3];
    const float* b1  = (const float*)d_in[4];
    const float* W2  = (const float*)d_in[5];
    const float* b2  = (const float*)d_in[6];
    const float* Wl  = (const float*)d_in[7];
    const float* bl  = (const float*)d_in[8];
    float* out = (float*)d_out;

    int N = in_sizes[0] / C;        // 100000
    int E = in_sizes[1] / 2;        // 1600000

    // graph build
    k_repack<<<256, 256>>>(ei, bat, E, N);
    k_init<<<256, 256>>>(N);
    k_hist<<<512, 256>>>(E);
    k_dinv<<<(N + 255) / 256, 256>>>(N);
    int nb = (N + 1023) / 1024;
    k_scan1<<<nb, 1024>>>(N);
    k_scan2<<<1, 128>>>(nb);
    k_scan3<<<(N + 255) / 256, 256>>>(N);
    k_fill<<<512, 256>>>(E);

    // layer 1
    k_gemm<<<(N + 63) / 64, 256>>>(x, W1, g_bufA, N);
    k_agg<<<(N * 32 + 255) / 256, 256>>>(g_bufA, b1, g_bufB, N);
    // layer 2
    k_gemm<<<(N + 63) / 64, 256>>>(g_bufB, W2, g_bufA, N);
    k_agg<<<(N * 32 + 255) / 256, 256>>>(g_bufA, b2, g_bufB, N);

    // pooling + head
    k_ghist<<<256, 256>>>(N);
    k_goff<<<1, 32>>>();
    k_pool<<<NG, C>>>(g_bufB);
    k_head<<<NG, OC>>>(Wl, bl, out);
}